// round 2
// baseline (speedup 1.0000x reference)
#include <cuda_runtime.h>
#include <math.h>

// YOLO-v1 loss: fused single-launch HBM-bound streaming reduction.
// predictions, target: [N, S, S, 30] fp32; output: scalar fp32.
//
// Persistent grid (NBLOCKS blocks, grid-stride over 128-cell tiles):
//   - stage tile into smem via coalesced float4 streaming loads (__ldcs)
//   - per-cell loss, block tree-reduce, accumulate per-block partial
//   - each block writes ONE partial; last block (atomic counter) reduces all
//     partials in double precision and writes d_out[0]. Fully deterministic:
//     tile->block map, per-block accumulation order, and final sum order are
//     all fixed. Counter is reset for graph replay.

#define DPC 30
#define CELLS_PER_TILE 128
#define NTHREADS 128
#define NBLOCKS 1036           // 148 SMs * 7 blocks/SM (smem-limited occupancy)

__device__ float g_partials[NBLOCKS];
__device__ unsigned int g_count;   // zero-init; reset by last block each launch

__device__ __forceinline__ float iou_sq(float x1, float y1, float w1,
                                        float x2, float y2, float w2) {
    float wi = fminf(x1 + w1, x2 + w2) - fmaxf(x1, x2);
    float hi = fminf(y1 + w1, y2 + w2) - fmaxf(y1, y2);
    float inter = wi * hi;
    float uni = w1 * w1 + w2 * w2 - inter;
    return (wi > 0.0f && hi > 0.0f) ? inter / uni : 0.0f;
}

__global__ void __launch_bounds__(NTHREADS)
yolo_loss_kernel(const float* __restrict__ pred,
                 const float* __restrict__ tgt,
                 int num_cells, float* __restrict__ out) {
    __shared__ float sp[CELLS_PER_TILE * DPC];   // 15360 B
    __shared__ float st[CELLS_PER_TILE * DPC];   // 15360 B
    __shared__ float warp_sums[NTHREADS / 32];
    __shared__ bool s_last;

    const int tid = threadIdx.x;
    const int ntiles = (num_cells + CELLS_PER_TILE - 1) / CELLS_PER_TILE;

    float block_acc = 0.0f;

    for (int tile = blockIdx.x; tile < ntiles; tile += NBLOCKS) {
        const long long cell0 = (long long)tile * CELLS_PER_TILE;
        const long long base = cell0 * DPC;

        int cells_here = num_cells - (int)cell0;
        if (cells_here > CELLS_PER_TILE) cells_here = CELLS_PER_TILE;
        const int nfloats = cells_here * DPC;

        // ---- coalesced float4 streaming stage ----
        // base byte offset = tile*128*120 bytes, multiple of 16 -> aligned.
        const float4* p4 = reinterpret_cast<const float4*>(pred + base);
        const float4* t4 = reinterpret_cast<const float4*>(tgt + base);
        float4* sp4 = reinterpret_cast<float4*>(sp);
        float4* st4 = reinterpret_cast<float4*>(st);
        const int n4 = nfloats >> 2;
        for (int i = tid; i < n4; i += NTHREADS) {
            sp4[i] = __ldcs(p4 + i);
            st4[i] = __ldcs(t4 + i);
        }
        for (int i = (n4 << 2) + tid; i < nfloats; i += NTHREADS) {
            sp[i] = __ldcs(pred + base + i);
            st[i] = __ldcs(tgt + base + i);
        }
        __syncthreads();

        // ---- per-cell loss ----
        float loss = 0.0f;
        if (tid < cells_here) {
            const float* p = sp + tid * DPC;
            const float* t = st + tid * DPC;

            const float t0 = t[0], t1 = t[1], t2 = t[2], t3 = t[3];
            const float obj = (t[4] == 1.0f) ? 1.0f : 0.0f;

            const float p0 = p[0], p1 = p[1], p2 = p[2], p3 = p[3], p4v = p[4];
            const float p5 = p[5], p6 = p[6], p7 = p[7], p8 = p[8], p9 = p[9];

            const float i1 = iou_sq(p0, p1, p2, t0, t1, t2);
            const float i2 = iou_sq(p5, p6, p7, t0, t1, t2);
            const bool c1 = i1 > i2;

            const float rx = c1 ? p0 : p5;
            const float ry = c1 ? p1 : p6;
            const float rw = c1 ? p2 : p7;
            const float rh = c1 ? p3 : p8;
            const float rc = c1 ? p4v : p9;
            const float oc = c1 ? p9 : p4v;

            const float dx = rx - t0, dy = ry - t1;
            loss += 5.0f * obj * (dx * dx + dy * dy);

            const float sw = sqrtf(fabsf(rw)) - sqrtf(t2);
            const float sh = sqrtf(fabsf(rh)) - sqrtf(t3);
            loss += 5.0f * obj * (sw * sw + sh * sh);

            const float dc = 1.0f - rc;
            loss += obj * dc * dc;

            loss += 0.5f * obj * oc * oc;
            loss += 0.5f * (1.0f - obj) * (p4v * p4v + p9 * p9);

            float cls = 0.0f;
            #pragma unroll
            for (int k = 10; k < 30; k++) {
                const float d = p[k] - t[k];
                cls += d * d;
            }
            loss += obj * cls;
        }

        // ---- block tree reduction (deterministic) ----
        #pragma unroll
        for (int off = 16; off > 0; off >>= 1)
            loss += __shfl_down_sync(0xFFFFFFFFu, loss, off);

        if ((tid & 31) == 0) warp_sums[tid >> 5] = loss;
        __syncthreads();
        if (tid == 0) {
            float s = 0.0f;
            #pragma unroll
            for (int w = 0; w < NTHREADS / 32; w++) s += warp_sums[w];
            block_acc += s;
        }
        __syncthreads();   // protect warp_sums/smem before next tile
    }

    // ---- publish partial, elect last block ----
    if (tid == 0) {
        g_partials[blockIdx.x] = block_acc;
        __threadfence();
        unsigned int done = atomicAdd(&g_count, 1u);
        s_last = (done == NBLOCKS - 1);
    }
    __syncthreads();

    if (s_last) {
        __shared__ double sd[NTHREADS];
        double acc = 0.0;
        for (int i = tid; i < NBLOCKS; i += NTHREADS)
            acc += (double)g_partials[i];
        sd[tid] = acc;
        __syncthreads();
        #pragma unroll
        for (int s = NTHREADS / 2; s > 0; s >>= 1) {
            if (tid < s) sd[tid] += sd[tid + s];
            __syncthreads();
        }
        if (tid == 0) {
            out[0] = (float)sd[0];
            g_count = 0;   // reset for next graph replay
        }
    }
}

extern "C" void kernel_launch(void* const* d_in, const int* in_sizes, int n_in,
                              void* d_out, int out_size) {
    const float* pred = (const float*)d_in[0];
    const float* tgt  = (const float*)d_in[1];
    float* out = (float*)d_out;

    const int num_cells = in_sizes[0] / DPC;   // 1,605,632

    yolo_loss_kernel<<<NBLOCKS, NTHREADS>>>(pred, tgt, num_cells, out);
}